// round 2
// baseline (speedup 1.0000x reference)
#include <cuda_runtime.h>
#include <math.h>

// Problem constants
#define T_TOK 16384
#define D_DIM 4096
#define E_EXP 256
#define G_GRP 8
#define EPG   32

// GEMM tiling
#define BM 128
#define BN 128
#define BK 32

// Scratch (static device globals are allowed; allocation is not)
__device__ float g_logits[T_TOK * E_EXP];   // 16 MB
__device__ float g_colsum[E_EXP];
__device__ float g_count[E_EXP];

// ---------------- f32x2 helpers ----------------
__device__ __forceinline__ void fma2(unsigned long long& d,
                                     unsigned long long a,
                                     unsigned long long b) {
    asm("fma.rn.f32x2 %0, %1, %2, %0;" : "+l"(d) : "l"(a), "l"(b));
}
__device__ __forceinline__ unsigned long long pack2(float x, float y) {
    unsigned long long r;
    asm("mov.b64 %0, {%1, %2};" : "=l"(r) : "f"(x), "f"(y));
    return r;
}
__device__ __forceinline__ void unpack2(unsigned long long v, float& lo, float& hi) {
    asm("mov.b64 {%0, %1}, %2;" : "=f"(lo), "=f"(hi) : "l"(v));
}

// ---------------- kernel 0: zero accumulators ----------------
__global__ void zero_kernel() {
    int i = threadIdx.x;
    if (i < E_EXP) { g_colsum[i] = 0.0f; g_count[i] = 0.0f; }
}

// ---------------- kernel 1: SGEMM (f32x2 packed) ----------------
// C[t,e] = sum_k x[t,k] * W[e,k];  x:[T,D] row-major, W:[E,D] row-major.
__global__ __launch_bounds__(256, 2)
void gemm_kernel(const float* __restrict__ x, const float* __restrict__ W) {
    __shared__ __align__(16) float As[BK][BM];
    __shared__ __align__(16) float Bs[BK][BN];

    const int tid = threadIdx.x;
    const int tx = tid & 15;   // 0..15 -> col octet
    const int ty = tid >> 4;   // 0..15 -> row octet
    const int m0 = blockIdx.y * BM;
    const int n0 = blockIdx.x * BN;

    // accumulators: pairs along M. acc[u][j] = (C[m+2u], C[m+2u+1]) for col j
    unsigned long long acc[4][8];
#pragma unroll
    for (int u = 0; u < 4; ++u)
#pragma unroll
        for (int j = 0; j < 8; ++j) acc[u][j] = 0ULL;

    for (int k0 = 0; k0 < D_DIM; k0 += BK) {
        // cooperative load: 128x32 floats each for A and B, transposed into smem
#pragma unroll
        for (int i = 0; i < 4; ++i) {
            int f  = tid + i * 256;           // float4 index (0..1023)
            int r  = f >> 3;                  // tile row (0..127)
            int c4 = f & 7;                   // float4 within row (0..7)
            float4 av = *(const float4*)&x[(size_t)(m0 + r) * D_DIM + k0 + c4 * 4];
            As[c4 * 4 + 0][r] = av.x;
            As[c4 * 4 + 1][r] = av.y;
            As[c4 * 4 + 2][r] = av.z;
            As[c4 * 4 + 3][r] = av.w;
            float4 bv = *(const float4*)&W[(size_t)(n0 + r) * D_DIM + k0 + c4 * 4];
            Bs[c4 * 4 + 0][r] = bv.x;
            Bs[c4 * 4 + 1][r] = bv.y;
            Bs[c4 * 4 + 2][r] = bv.z;
            Bs[c4 * 4 + 3][r] = bv.w;
        }
        __syncthreads();

#pragma unroll 8
        for (int kk = 0; kk < BK; ++kk) {
            // a pairs: LDS.64, broadcast across warp (address depends on ty only)
            unsigned long long ap[4];
#pragma unroll
            for (int u = 0; u < 4; ++u)
                ap[u] = *(const unsigned long long*)&As[kk][ty * 8 + 2 * u];
            // b values: 2x LDS.128, then broadcast-pack
            float bb[8];
            *(float4*)&bb[0] = *(const float4*)&Bs[kk][tx * 8];
            *(float4*)&bb[4] = *(const float4*)&Bs[kk][tx * 8 + 4];
            unsigned long long bp[8];
#pragma unroll
            for (int j = 0; j < 8; ++j) bp[j] = pack2(bb[j], bb[j]);
#pragma unroll
            for (int u = 0; u < 4; ++u)
#pragma unroll
                for (int j = 0; j < 8; ++j) fma2(acc[u][j], ap[u], bp[j]);
        }
        __syncthreads();
    }

    // store: rows m0+ty*8 .. +7, cols n0+tx*8 .. +7
#pragma unroll
    for (int u = 0; u < 4; ++u) {
        float lo[8], hi[8];
#pragma unroll
        for (int j = 0; j < 8; ++j) unpack2(acc[u][j], lo[j], hi[j]);
        size_t r0 = (size_t)(m0 + ty * 8 + 2 * u) * E_EXP + n0 + tx * 8;
        size_t r1 = r0 + E_EXP;
        *(float4*)&g_logits[r0]     = make_float4(lo[0], lo[1], lo[2], lo[3]);
        *(float4*)&g_logits[r0 + 4] = make_float4(lo[4], lo[5], lo[6], lo[7]);
        *(float4*)&g_logits[r1]     = make_float4(hi[0], hi[1], hi[2], hi[3]);
        *(float4*)&g_logits[r1 + 4] = make_float4(hi[4], hi[5], hi[6], hi[7]);
    }
}

// ---------------- kernel 2: router epilogue ----------------
// One warp per token. Lane l owns experts 8l..8l+7; lanes 4g..4g+3 cover group g.
__device__ __forceinline__ bool better(float v, int i, float w, int j) {
    return (v > w) || (v == w && i < j);
}

__global__ __launch_bounds__(1024)
void router_kernel(float* __restrict__ out) {
    __shared__ float s_col[E_EXP];
    __shared__ float s_hist[E_EXP];
    const int tid = threadIdx.x;
    if (tid < E_EXP) { s_col[tid] = 0.0f; s_hist[tid] = 0.0f; }
    __syncthreads();

    const int warp = tid >> 5;
    const int lane = tid & 31;
    const int t = blockIdx.x * 32 + warp;
    const unsigned FULL = 0xFFFFFFFFu;

    // load 8 logits for this lane
    float l[8];
    {
        const float* row = &g_logits[(size_t)t * E_EXP + lane * 8];
        *(float4*)&l[0] = *(const float4*)&row[0];
        *(float4*)&l[4] = *(const float4*)&row[4];
    }

    // softmax (max-subtracted)
    float m = l[0];
#pragma unroll
    for (int j = 1; j < 8; ++j) m = fmaxf(m, l[j]);
#pragma unroll
    for (int off = 16; off > 0; off >>= 1) m = fmaxf(m, __shfl_xor_sync(FULL, m, off));
    float p[8];
    float s = 0.0f;
#pragma unroll
    for (int j = 0; j < 8; ++j) { p[j] = expf(l[j] - m); s += p[j]; }
#pragma unroll
    for (int off = 16; off > 0; off >>= 1) s += __shfl_xor_sync(FULL, s, off);
    float invs = 1.0f / s;
#pragma unroll
    for (int j = 0; j < 8; ++j) p[j] *= invs;

    // column sums for aux loss
#pragma unroll
    for (int j = 0; j < 8; ++j) atomicAdd(&s_col[lane * 8 + j], p[j]);

    // lane-local top-2 (index tie-break: first occurrence wins via strict >)
    float v1 = -1e30f, v2 = -1e30f;
    int i1 = 0, i2 = 0;
#pragma unroll
    for (int j = 0; j < 8; ++j) {
        int e = lane * 8 + j;
        if (p[j] > v1)      { v2 = v1; i2 = i1; v1 = p[j]; i1 = e; }
        else if (p[j] > v2) { v2 = p[j]; i2 = e; }
    }

    // butterfly merge within the quad (4 lanes = 1 group of 32 experts)
#pragma unroll
    for (int d = 1; d <= 2; d <<= 1) {
        float w1 = __shfl_xor_sync(FULL, v1, d);
        int   k1 = __shfl_xor_sync(FULL, i1, d);
        float w2 = __shfl_xor_sync(FULL, v2, d);
        int   k2 = __shfl_xor_sync(FULL, i2, d);
        if (better(w1, k1, v1, i1)) {
            if (better(v1, i1, w2, k2)) { v2 = v1; i2 = i1; }
            else                        { v2 = w2; i2 = k2; }
            v1 = w1; i1 = k1;
        } else if (better(w1, k1, v2, i2)) {
            v2 = w1; i2 = k1;
        }
    }

    // group scores (sum of group's top-2), broadcast to all lanes
    float gscore = v1 + v2;
    float gs[G_GRP];
#pragma unroll
    for (int g = 0; g < G_GRP; ++g) gs[g] = __shfl_sync(FULL, gscore, g * 4);

    // top-4 groups, lower index first on ties (strict > with ascending scan)
    int sel[4];
    bool used[G_GRP];
#pragma unroll
    for (int g = 0; g < G_GRP; ++g) used[g] = false;
    float wsum = 0.0f;
#pragma unroll
    for (int r = 0; r < 4; ++r) {
        int best = -1; float bv = -1e30f;
#pragma unroll
        for (int g = 0; g < G_GRP; ++g)
            if (!used[g] && gs[g] > bv) { bv = gs[g]; best = g; }
        sel[r] = best; used[best] = true; wsum += bv;
    }
    float invw = 1.0f / (wsum + 1e-9f);

    // gather selected groups' top-2 (all lanes execute the shuffles)
    int rr  = lane & 3;
    int src = sel[rr] * 4;
    float fv1 = __shfl_sync(FULL, v1, src);
    int   fi1 = __shfl_sync(FULL, i1, src);
    float fv2 = __shfl_sync(FULL, v2, src);
    int   fi2 = __shfl_sync(FULL, i2, src);

    float* out_w = out;
    float* out_i = out + (size_t)T_TOK * 8;
    if (lane < 4) {
        size_t b = (size_t)t * 8 + 2 * lane;
        out_w[b]     = fv1 * invw;
        out_w[b + 1] = fv2 * invw;
        out_i[b]     = (float)fi1;
        out_i[b + 1] = (float)fi2;
    }
    if (lane == 0) atomicAdd(&s_hist[fi1], 1.0f);

    __syncthreads();
    if (tid < E_EXP) {
        atomicAdd(&g_colsum[tid], s_col[tid]);
        if (s_hist[tid] != 0.0f) atomicAdd(&g_count[tid], s_hist[tid]);
    }
}

// ---------------- kernel 3: aux loss ----------------
__global__ void aux_kernel(float* __restrict__ out) {
    __shared__ float red[8];
    int tid = threadIdx.x;
    float v = g_count[tid] * g_colsum[tid];
#pragma unroll
    for (int off = 16; off > 0; off >>= 1) v += __shfl_xor_sync(0xFFFFFFFFu, v, off);
    if ((tid & 31) == 0) red[tid >> 5] = v;
    __syncthreads();
    if (tid == 0) {
        float tot = 0.0f;
#pragma unroll
        for (int i = 0; i < 8; ++i) tot += red[i];
        out[(size_t)T_TOK * 16] = (float)E_EXP * tot / ((float)T_TOK * (float)T_TOK);
    }
}

// ---------------- launcher ----------------
extern "C" void kernel_launch(void* const* d_in, const int* in_sizes, int n_in,
                              void* d_out, int out_size) {
    const float* x = (const float*)d_in[0];
    const float* W = (const float*)d_in[1];
    float* out = (float*)d_out;

    zero_kernel<<<1, 256>>>();
    gemm_kernel<<<dim3(E_EXP / BN, T_TOK / BM), 256>>>(x, W);
    router_kernel<<<T_TOK / 32, 1024>>>(out);
    aux_kernel<<<1, 256>>>(out);
}